// round 10
// baseline (speedup 1.0000x reference)
#include <cuda_runtime.h>
#include <cuda_bf16.h>

#define BB 512
#define TT 4096
#define RR 16
#define NCH 8                       // chunks per batch
#define ROWS_PER_CHUNK (TT / NCH)   // 512 rows per block
#define THREADS 256                 // 8 warps; warp covers 64 rows (4 iters x 16 rows)

// Scratch: per-(b, chunk) partial sums of (var_p - var_t)^2, plus per-b n.
__device__ __align__(16) float g_partial[BB * NCH];
__device__ float g_n[BB];

__global__ __launch_bounds__(THREADS) void rcl_partial_kernel(
    const float* __restrict__ pred,
    const float* __restrict__ target,
    const float* __restrict__ mask)
{
    // Let the dependent (final) kernel begin launching immediately; it still
    // waits for this grid's completion+flush in cudaGridDependencySynchronize().
    cudaTriggerProgrammaticLaunchCompletion();

    const int b    = blockIdx.y;
    const int ch   = blockIdx.x;
    const int tid  = threadIdx.x;
    const int lane = tid & 31;
    const int wid  = tid >> 5;
    const int h    = lane & 1;        // which half-row [8h, 8h+8) this lane owns

    // ---- per-b mask stats (L1-broadcast, once per thread) ----
    const float4* m4 = reinterpret_cast<const float4*>(mask + (size_t)b * RR);
    float4 mall[4];
#pragma unroll
    for (int i = 0; i < 4; i++) mall[i] = __ldg(&m4[i]);
    const float* mf = reinterpret_cast<const float*>(mall);
    float n = 0.0f;
#pragma unroll
    for (int r = 0; r < RR; r++) n += mf[r];
    const float4 m0 = mall[2 * h];
    const float4 m1 = mall[2 * h + 1];

    const float n_safe  = fmaxf(n, 2.0f);
    const float inv_ns  = 1.0f / n_safe;
    const float inv_nm1 = 1.0f / (n_safe - 1.0f);

    if (ch == 0 && tid == 0) g_n[b] = n;   // single writer per b

    // ---- this warp's 64 rows: 16 rows per iteration, half-row per lane ----
    const int    row0  = ch * ROWS_PER_CHUNK + wid * 64;
    const size_t fbase = ((size_t)b * TT + (size_t)row0) * RR;   // float index
    const float4* p4 = reinterpret_cast<const float4*>(pred + fbase);
    const float4* q4 = reinterpret_cast<const float4*>(target + fbase);

    float acc = 0.0f;

#pragma unroll 2
    for (int it = 0; it < 4; ++it) {
        // lane (pair = lane>>1, half = h) owns row (it*16 + pair), floats [8h, 8h+8)
        const int i0 = it * 64 + 4 * (lane >> 1) + 2 * h;
        const float4 a0 = __ldcs(&p4[i0]);
        const float4 a1 = __ldcs(&p4[i0 + 1]);
        const float4 c0 = __ldcs(&q4[i0]);
        const float4 c1 = __ldcs(&q4[i0 + 1]);

        // masked partial moments over this lane's 8 elements
        float sp  = m0.x * a0.x + m0.y * a0.y + m0.z * a0.z + m0.w * a0.w
                  + m1.x * a1.x + m1.y * a1.y + m1.z * a1.z + m1.w * a1.w;
        float spp = fmaf(m0.x * a0.x, a0.x, fmaf(m0.y * a0.y, a0.y,
                    fmaf(m0.z * a0.z, a0.z, fmaf(m0.w * a0.w, a0.w,
                    fmaf(m1.x * a1.x, a1.x, fmaf(m1.y * a1.y, a1.y,
                    fmaf(m1.z * a1.z, a1.z, (m1.w * a1.w) * a1.w)))))));
        float st  = m0.x * c0.x + m0.y * c0.y + m0.z * c0.z + m0.w * c0.w
                  + m1.x * c1.x + m1.y * c1.y + m1.z * c1.z + m1.w * c1.w;
        float stt = fmaf(m0.x * c0.x, c0.x, fmaf(m0.y * c0.y, c0.y,
                    fmaf(m0.z * c0.z, c0.z, fmaf(m0.w * c0.w, c0.w,
                    fmaf(m1.x * c1.x, c1.x, fmaf(m1.y * c1.y, c1.y,
                    fmaf(m1.z * c1.z, c1.z, (m1.w * c1.w) * c1.w)))))));

        // one butterfly step across the half-row pair -> full-row sums
        sp  += __shfl_xor_sync(0xFFFFFFFFu, sp,  1);
        spp += __shfl_xor_sync(0xFFFFFFFFu, spp, 1);
        st  += __shfl_xor_sync(0xFFFFFFFFu, st,  1);
        stt += __shfl_xor_sync(0xFFFFFFFFu, stt, 1);

        const float mp  = sp * inv_ns;
        const float mt  = st * inv_ns;
        // sum m*(x-mean)^2 = sxx - 2*mean*sx + mean^2 * n
        const float sqp = spp - 2.0f * mp * sp + mp * mp * n;
        const float sqt = stt - 2.0f * mt * st + mt * mt * n;
        const float d   = (sqp - sqt) * inv_nm1;   // var_p - var_t
        acc = fmaf(d, d, acc);
    }

    acc *= 0.5f;   // each row's d^2 is replicated in both lanes of its pair

    // ---- deterministic block reduction ----
#pragma unroll
    for (int off = 16; off > 0; off >>= 1)
        acc += __shfl_down_sync(0xFFFFFFFFu, acc, off);

    __shared__ float swarp[THREADS / 32];
    if (lane == 0) swarp[wid] = acc;
    __syncthreads();

    if (wid == 0) {
        float v = (lane < (THREADS / 32)) ? swarp[lane] : 0.0f;
#pragma unroll
        for (int off = 4; off > 0; off >>= 1)
            v += __shfl_down_sync(0xFFFFFFFFu, v, off);
        if (lane == 0) g_partial[b * NCH + ch] = v;
    }
}

__global__ __launch_bounds__(BB) void rcl_final_kernel(float* __restrict__ out)
{
    // Wait for the primary grid to complete and flush its memory.
    cudaGridDependencySynchronize();

    const int b = threadIdx.x;   // 512 threads, one per batch

    // 3 independent loads: 2x float4 partials + 1 scalar n (all L2-hot)
    const float4* gp4 = reinterpret_cast<const float4*>(&g_partial[b * NCH]);
    const float4 s0 = __ldcg(&gp4[0]);
    const float4 s1 = __ldcg(&gp4[1]);
    const float  nb = __ldcg(&g_n[b]);

    const float s = (s0.x + s0.y + s0.z + s0.w) + (s1.x + s1.y + s1.z + s1.w);
    const float mse = s * (1.0f / (float)TT);

    const float valid = (nb > 1.0f) ? 1.0f : 0.0f;
    float tot = valid * mse;
    float cnt = valid;

#pragma unroll
    for (int off = 16; off > 0; off >>= 1) {
        tot += __shfl_down_sync(0xFFFFFFFFu, tot, off);
        cnt += __shfl_down_sync(0xFFFFFFFFu, cnt, off);
    }

    __shared__ float stot[BB / 32];
    __shared__ float scnt[BB / 32];
    const int lane = threadIdx.x & 31;
    const int wid  = threadIdx.x >> 5;
    if (lane == 0) { stot[wid] = tot; scnt[wid] = cnt; }
    __syncthreads();

    if (wid == 0) {
        float vt = (lane < (BB / 32)) ? stot[lane] : 0.0f;
        float vc = (lane < (BB / 32)) ? scnt[lane] : 0.0f;
#pragma unroll
        for (int off = 8; off > 0; off >>= 1) {
            vt += __shfl_down_sync(0xFFFFFFFFu, vt, off);
            vc += __shfl_down_sync(0xFFFFFFFFu, vc, off);
        }
        if (lane == 0) {
            const float loss = (vc > 0.0f) ? (vt / fmaxf(vc, 1.0f)) : 0.0f;
            out[0] = 0.1f * loss;
        }
    }
}

extern "C" void kernel_launch(void* const* d_in, const int* in_sizes, int n_in,
                              void* d_out, int out_size)
{
    const float* pred   = (const float*)d_in[0];
    const float* target = (const float*)d_in[1];
    const float* mask   = (const float*)d_in[2];
    float* out = (float*)d_out;

    dim3 grid(NCH, BB);
    rcl_partial_kernel<<<grid, THREADS>>>(pred, target, mask);

    // Final kernel with Programmatic Dependent Launch: launch overlaps the
    // primary's tail; cudaGridDependencySynchronize() provides the ordering.
    cudaLaunchConfig_t cfg = {};
    cfg.gridDim  = dim3(1, 1, 1);
    cfg.blockDim = dim3(BB, 1, 1);
    cfg.dynamicSmemBytes = 0;
    cfg.stream = 0;
    cudaLaunchAttribute attr[1];
    attr[0].id = cudaLaunchAttributeProgrammaticStreamSerialization;
    attr[0].val.programmaticStreamSerializationAllowed = 1;
    cfg.attrs = attr;
    cfg.numAttrs = 1;
    cudaLaunchKernelEx(&cfg, rcl_final_kernel, out);
}

// round 11
// speedup vs baseline: 1.0054x; 1.0054x over previous
#include <cuda_runtime.h>
#include <cuda_bf16.h>

#define BB 512
#define TT 4096
#define RR 16
#define NCH 32                      // chunks per batch
#define ROWS_PER_CHUNK (TT / NCH)   // 128 rows per block
#define THREADS 256                 // 8 warps; warp covers 16 rows (one tile)

// Scratch: per-(b, chunk) partial sums of (var_p - var_t)^2, plus per-b n.
__device__ __align__(16) float g_partial[BB * NCH];
__device__ float g_n[BB];

__global__ __launch_bounds__(THREADS) void rcl_partial_kernel(
    const float* __restrict__ pred,
    const float* __restrict__ target,
    const float* __restrict__ mask)
{
    const int b    = blockIdx.y;
    const int ch   = blockIdx.x;
    const int tid  = threadIdx.x;
    const int lane = tid & 31;
    const int wid  = tid >> 5;
    const int h    = lane & 1;        // which half-row [8h, 8h+8) this lane owns

    // ---- per-b mask stats (L1-broadcast, once per thread) ----
    const float4* m4 = reinterpret_cast<const float4*>(mask + (size_t)b * RR);
    float4 mall[4];
#pragma unroll
    for (int i = 0; i < 4; i++) mall[i] = __ldg(&m4[i]);
    const float* mf = reinterpret_cast<const float*>(mall);
    float n = 0.0f;
#pragma unroll
    for (int r = 0; r < RR; r++) n += mf[r];
    const float4 m0 = mall[2 * h];
    const float4 m1 = mall[2 * h + 1];

    const float n_safe  = fmaxf(n, 2.0f);
    const float inv_ns  = 1.0f / n_safe;
    const float inv_nm1 = 1.0f / (n_safe - 1.0f);

    if (ch == 0 && tid == 0) g_n[b] = n;   // single writer per b

    // ---- this warp's 16 rows: half-row per lane, fully coalesced ----
    const int    row0  = ch * ROWS_PER_CHUNK + wid * 16;
    const size_t fbase = ((size_t)b * TT + (size_t)row0) * RR;   // float index
    const float4* p4 = reinterpret_cast<const float4*>(pred + fbase);
    const float4* q4 = reinterpret_cast<const float4*>(target + fbase);

    // lane (pair = lane>>1, half = h) owns row (pair), floats [8h, 8h+8)
    const int i0 = 4 * (lane >> 1) + 2 * h;
    const float4 a0 = __ldcs(&p4[i0]);
    const float4 a1 = __ldcs(&p4[i0 + 1]);
    const float4 c0 = __ldcs(&q4[i0]);
    const float4 c1 = __ldcs(&q4[i0 + 1]);

    // masked partial moments over this lane's 8 elements
    float sp  = m0.x * a0.x + m0.y * a0.y + m0.z * a0.z + m0.w * a0.w
              + m1.x * a1.x + m1.y * a1.y + m1.z * a1.z + m1.w * a1.w;
    float spp = fmaf(m0.x * a0.x, a0.x, fmaf(m0.y * a0.y, a0.y,
                fmaf(m0.z * a0.z, a0.z, fmaf(m0.w * a0.w, a0.w,
                fmaf(m1.x * a1.x, a1.x, fmaf(m1.y * a1.y, a1.y,
                fmaf(m1.z * a1.z, a1.z, (m1.w * a1.w) * a1.w)))))));
    float st  = m0.x * c0.x + m0.y * c0.y + m0.z * c0.z + m0.w * c0.w
              + m1.x * c1.x + m1.y * c1.y + m1.z * c1.z + m1.w * c1.w;
    float stt = fmaf(m0.x * c0.x, c0.x, fmaf(m0.y * c0.y, c0.y,
                fmaf(m0.z * c0.z, c0.z, fmaf(m0.w * c0.w, c0.w,
                fmaf(m1.x * c1.x, c1.x, fmaf(m1.y * c1.y, c1.y,
                fmaf(m1.z * c1.z, c1.z, (m1.w * c1.w) * c1.w)))))));

    // one butterfly step across the half-row pair -> full-row sums
    sp  += __shfl_xor_sync(0xFFFFFFFFu, sp,  1);
    spp += __shfl_xor_sync(0xFFFFFFFFu, spp, 1);
    st  += __shfl_xor_sync(0xFFFFFFFFu, st,  1);
    stt += __shfl_xor_sync(0xFFFFFFFFu, stt, 1);

    const float mp  = sp * inv_ns;
    const float mt  = st * inv_ns;
    // sum m*(x-mean)^2 = sxx - 2*mean*sx + mean^2 * n
    const float sqp = spp - 2.0f * mp * sp + mp * mp * n;
    const float sqt = stt - 2.0f * mt * st + mt * mt * n;
    const float d   = (sqp - sqt) * inv_nm1;   // var_p - var_t
    float acc = d * d * 0.5f;   // each row's d^2 lives in both lanes of its pair

    // ---- deterministic block reduction ----
#pragma unroll
    for (int off = 16; off > 0; off >>= 1)
        acc += __shfl_down_sync(0xFFFFFFFFu, acc, off);

    __shared__ float swarp[THREADS / 32];
    if (lane == 0) swarp[wid] = acc;
    __syncthreads();

    if (wid == 0) {
        float v = (lane < (THREADS / 32)) ? swarp[lane] : 0.0f;
#pragma unroll
        for (int off = 4; off > 0; off >>= 1)
            v += __shfl_down_sync(0xFFFFFFFFu, v, off);
        if (lane == 0) g_partial[b * NCH + ch] = v;
    }
}

__global__ __launch_bounds__(BB) void rcl_final_kernel(float* __restrict__ out)
{
    const int b = threadIdx.x;   // 512 threads, one per batch

    // 8x float4 partials + 1 scalar n, all independent, L2-hot
    const float4* gp4 = reinterpret_cast<const float4*>(&g_partial[b * NCH]);
    float4 sv[NCH / 4];
#pragma unroll
    for (int i = 0; i < NCH / 4; i++) sv[i] = __ldcg(&gp4[i]);
    const float nb = __ldcg(&g_n[b]);

    float s = 0.0f;
#pragma unroll
    for (int i = 0; i < NCH / 4; i++)
        s += (sv[i].x + sv[i].y) + (sv[i].z + sv[i].w);
    const float mse = s * (1.0f / (float)TT);

    const float valid = (nb > 1.0f) ? 1.0f : 0.0f;
    float tot = valid * mse;
    float cnt = valid;

#pragma unroll
    for (int off = 16; off > 0; off >>= 1) {
        tot += __shfl_down_sync(0xFFFFFFFFu, tot, off);
        cnt += __shfl_down_sync(0xFFFFFFFFu, cnt, off);
    }

    __shared__ float stot[BB / 32];
    __shared__ float scnt[BB / 32];
    const int lane = threadIdx.x & 31;
    const int wid  = threadIdx.x >> 5;
    if (lane == 0) { stot[wid] = tot; scnt[wid] = cnt; }
    __syncthreads();

    if (wid == 0) {
        float vt = (lane < (BB / 32)) ? stot[lane] : 0.0f;
        float vc = (lane < (BB / 32)) ? scnt[lane] : 0.0f;
#pragma unroll
        for (int off = 8; off > 0; off >>= 1) {
            vt += __shfl_down_sync(0xFFFFFFFFu, vt, off);
            vc += __shfl_down_sync(0xFFFFFFFFu, vc, off);
        }
        if (lane == 0) {
            const float loss = (vc > 0.0f) ? (vt / fmaxf(vc, 1.0f)) : 0.0f;
            out[0] = 0.1f * loss;
        }
    }
}

extern "C" void kernel_launch(void* const* d_in, const int* in_sizes, int n_in,
                              void* d_out, int out_size)
{
    const float* pred   = (const float*)d_in[0];
    const float* target = (const float*)d_in[1];
    const float* mask   = (const float*)d_in[2];
    float* out = (float*)d_out;

    dim3 grid(NCH, BB);
    rcl_partial_kernel<<<grid, THREADS>>>(pred, target, mask);
    rcl_final_kernel<<<1, BB>>>(out);
}